// round 3
// baseline (speedup 1.0000x reference)
#include <cuda_runtime.h>
#include <cstdint>

#define TT 1024
#define BB 128
#define CC 256
#define SS 128
#define LL 257          // 2*S+1 extended states
#define NTHR 288        // 9 warps x 32 lanes, one state per lane
#define NW 9
#define RD 8            // boundary ring depth (power of 2)
#define PF 8            // emission LDG prefetch depth (matches unroll)
#define LOG2E 1.4426950408889634f
#define LN2F  0.6931471805599453f
#define NEG2  (-1.0e9f) // very negative in log2 units (finite)

__device__ float g_loss[BB];
__device__ int   g_done;      // zero-init; last block resets it each launch

__device__ __forceinline__ float fexp2(float x){ float y; asm("ex2.approx.ftz.f32 %0, %1;" : "=f"(y) : "f"(x)); return y; }
__device__ __forceinline__ float flog2(float x){ float y; asm("lg2.approx.f32 %0, %1;" : "=f"(y) : "f"(x)); return y; }

__global__ void __launch_bounds__(NTHR, 1) ctc_fwd(
    const float* __restrict__ lp, const int* __restrict__ y,
    const int* __restrict__ ilen, const int* __restrict__ tlen,
    float* __restrict__ out)
{
  __shared__ unsigned long long slots[NW - 1][RD]; // {seq | val<<32}, written by warp w for warp w+1
  __shared__ int   prog[NW];                       // consumer progress (backpressure)
  __shared__ float fin[NTHR];                      // final alpha staging
  __shared__ float red[4];
  __shared__ int   lastblk;

  const int b    = blockIdx.x;
  const int tid  = threadIdx.x;
  const int w    = tid >> 5;
  const int lane = tid & 31;
  const int s    = tid;                            // extended state index
  const int len  = ilen[b];
  const int tl   = tlen[b];

  // init sync smem
  if (tid < (NW - 1) * RD) ((unsigned long long*)slots)[tid] = 0ull;
  if (tid < NW) prog[tid] = 0;

  // Per-lane class + skip flag
  int cls = 0; bool skipok = false;
  if (s < LL && (s & 1)) {
    int k = s >> 1;
    cls = y[b * SS + k];
    if (s >= 3) skipok = (cls != y[b * SS + k - 1]);
  }
  const float* base = lp + (size_t)b * CC + cls;   // per-lane gather base

  __syncthreads();                                 // slots/prog visible before first publish/poll

  // t = 0 init (log2 domain): only s=0,1 reachable
  float a = NEG2;
  if (s < 2) a = __ldg(base) * LOG2E;              // lane0: blank, lane1: y[0]

  // publish boundary for consumer's step t=1
  if (w < NW - 1 && lane == 31)
    *(volatile unsigned long long*)&slots[w][1 & (RD - 1)] =
        ((unsigned long long)__float_as_uint(a) << 32) | 1u;

  // emission prefetch pipeline: lpbuf[j] holds lp for step t=1+j
  float lpbuf[PF];
  #pragma unroll
  for (int j = 0; j < PF; ++j)
    lpbuf[j] = __ldg(base + (size_t)(1 + j) * (BB * CC));

  float sh1 = __shfl_up_sync(0xffffffffu, a, 1);
  float sh2 = __shfl_up_sync(0xffffffffu, a, 2);

  int t = 1;
  int last_seen = 0;                               // cached prog[w+1]

  while (t < len) {
    #pragma unroll
    for (int j = 0; j < PF; ++j) {
      if (t < len) {                               // uniform per block
        float emit = lpbuf[j] * LOG2E;
        int pr = t + PF;
        if (pr < TT) lpbuf[j] = __ldg(base + (size_t)pr * (BB * CC));  // off critical path

        float a1 = sh1;
        float a2v = sh2;
        if (lane < 2) {
          float bv = NEG2;
          if (w > 0) {                             // poll left neighbor's boundary value
            unsigned long long v;
            const volatile unsigned long long* ps = &slots[w - 1][t & (RD - 1)];
            do { v = *ps; } while ((unsigned)v != (unsigned)t);
            bv = __uint_as_float((unsigned)(v >> 32));
          }
          if (lane == 0) a1 = bv; else a2v = bv;   // lane0: alpha[s-1]; lane1: alpha[s-2]
        }
        float a2 = skipok ? a2v : NEG2;            // even boundary states: skipok=false anyway

        float m   = fmaxf(a, fmaxf(a1, a2));
        float sum = fexp2(a - m) + fexp2(a1 - m) + fexp2(a2 - m);
        a = m + flog2(sum) + emit;

        // publish alpha_t[top] for consumer's step t+1 (early, off own chain)
        if (w < NW - 1 && lane == 31) {
          if (last_seen < t + 1 - RD) {            // backpressure: don't overwrite unconsumed slot
            do { last_seen = ((volatile int*)prog)[w + 1]; } while (last_seen < t + 1 - RD);
          }
          *(volatile unsigned long long*)&slots[w][(t + 1) & (RD - 1)] =
              ((unsigned long long)__float_as_uint(a) << 32) | (unsigned)(t + 1);
        }
        if (w > 0 && lane == 0) ((volatile int*)prog)[w] = t;

        sh1 = __shfl_up_sync(0xffffffffu, a, 1);
        sh2 = __shfl_up_sync(0xffffffffu, a, 2);
        ++t;
      }
    }
  }

  fin[tid] = a;
  __syncthreads();

  if (tid == 0) {
    float ahi = fin[2 * tl];                       // state 2*tl
    float alo = fin[2 * tl - 1];                   // state 2*tl-1
    float m = fmaxf(ahi, alo);
    float ll2 = m + flog2(fexp2(ahi - m) + fexp2(alo - m));
    float loss = -ll2 * LN2F;
    if (!(loss < 0.5e9f)) loss = 0.f;              // zero_infinity (also inf/nan)
    g_loss[b] = loss / (float)tl;

    __threadfence();
    int old = atomicAdd(&g_done, 1);
    int isl = (old == BB - 1);
    if (isl) g_done = 0;                           // reset for next graph replay
    lastblk = isl;
  }
  __syncthreads();

  if (lastblk) {                                   // fused mean reduction in last block
    __threadfence();
    float v = (tid < BB) ? g_loss[tid] : 0.f;
    #pragma unroll
    for (int o = 16; o > 0; o >>= 1) v += __shfl_down_sync(0xffffffffu, v, o);
    if (lane == 0 && tid < BB) red[tid >> 5] = v;
    __syncthreads();
    if (tid == 0) out[0] = (red[0] + red[1] + red[2] + red[3]) * (1.0f / (float)BB);
  }
}

extern "C" void kernel_launch(void* const* d_in, const int* in_sizes, int n_in,
                              void* d_out, int out_size)
{
  const float* lp = (const float*)d_in[0];
  const int*   yy = (const int*)  d_in[1];
  const int*   il = (const int*)  d_in[2];
  const int*   tl = (const int*)  d_in[3];
  ctc_fwd<<<BB, NTHR>>>(lp, yy, il, tl, (float*)d_out);
}

// round 5
// speedup vs baseline: 4.9997x; 4.9997x over previous
#include <cuda_runtime.h>
#include <cstdint>

#define TT 1024
#define BB 128
#define CC 256
#define SS 128
#define NTHR 192        // 6 warps
#define WIN 10          // steps per sync window (halo overlap 24 supports up to 12)
#define RROWS 40        // row ring: 4 windows of 10 rows (40KB)
#define LOG2E 1.4426950408889634f
#define LN2F  0.6931471805599453f
#define NEG2  (-1.0e9f)

__device__ float g_loss[BB];
__device__ int   g_done;          // zero-init; nets to zero every launch

static __device__ __forceinline__ float fexp2(float x){ float y; asm("ex2.approx.ftz.f32 %0, %1;" : "=f"(y) : "f"(x)); return y; }
static __device__ __forceinline__ float flog2(float x){ float y; asm("lg2.approx.f32 %0, %1;" : "=f"(y) : "f"(x)); return y; }
static __device__ __forceinline__ void cp16(unsigned dst, const float* src){
  asm volatile("cp.async.cg.shared.global [%0], [%1], 16;" :: "r"(dst), "l"(src));
}
static __device__ __forceinline__ void cp_commit(){ asm volatile("cp.async.commit_group;"); }
template<int N> static __device__ __forceinline__ void cp_wait(){ asm volatile("cp.async.wait_group %0;" :: "n"(N)); }

__global__ void __launch_bounds__(NTHR, 1) ctc_fwd(
    const float* __restrict__ lp, const int* __restrict__ y,
    const int* __restrict__ ilen, const int* __restrict__ tlen,
    float* __restrict__ out)
{
  __shared__ __align__(16) float rows[RROWS][CC];  // 40KB emission row ring
  __shared__ float alphA[280];                     // alpha exchange, double-buffered
  __shared__ float alphB[280];
  __shared__ float red[8];
  __shared__ int   lastblk;

  const int b    = blockIdx.x;
  const int tid  = threadIdx.x;
  const int w    = tid >> 5;
  const int lane = tid & 31;
  const int len  = ilen[b];
  const int tl   = tlen[b];

  const int bw = 40 * w;                 // strip base (even state)
  const int s0 = bw + 2 * lane;          // even state (blank)
  const int s1 = s0 + 1;                 // odd state (label)
  const int own_lo = w ? bw + 24 : 0;    // owned partition: [own_lo, bw+64)
  const int own_hi = bw + 64;
  const bool ow0 = (s0 >= own_lo) & (s0 < own_hi);
  const bool ow1 = (s1 >= own_lo) & (s1 < own_hi);
  const bool lowcut = (w == 0) & (lane == 0);   // state 0 has no s-1

  // label class + skip flag for the odd state
  int idx  = s0 >> 1;                    // label index of s1
  int idxc = idx < SS ? idx : SS - 1;
  int im1  = idxc >= 1 ? idxc - 1 : 0;
  int cls  = y[b * SS + idxc];
  int clsp = y[b * SS + im1];
  bool skipok = (idx >= 1) && (idx < SS) && (cls != clsp);

  const float* gb = lp + (size_t)b * CC;
  const unsigned rows_u = (unsigned)__cvta_generic_to_shared(&rows[0][0]);

  // issue one 10-row window as one commit group (coalesced 16B chunks)
  auto issue_win = [&](int wt) {
    int bslot = ((wt / WIN) & 3) * WIN;  // ring position of this window
    #pragma unroll
    for (int k = 0; k < 4; ++k) {
      int c = tid + k * NTHR;            // chunk id, 640 chunks of 16B
      if (c < WIN * 64) {
        int r   = c >> 6;
        int off = (c & 63) * 16;         // byte offset within row
        int row = wt + r;
        if (row < TT)
          cp16(rows_u + (unsigned)((bslot + r) * (CC * 4) + off),
               gb + (size_t)row * (BB * CC) + (off >> 2));
      }
    }
    cp_commit();
  };

  // prologue: windows 0 and 1 in flight; window 0 resident after wait+bar
  issue_win(0);
  issue_win(WIN);
  cp_wait<1>();
  __syncthreads();

  // t=0 init (log2 domain): only global states 0 and 1 reachable
  float a0 = NEG2, a1 = NEG2;
  if (s0 == 0) a0 = rows[0][0]   * LOG2E;
  if (s1 == 1) a1 = rows[0][cls] * LOG2E;

  for (int wt = 0; wt < len; wt += WIN) {
    const int wi  = wt / WIN;
    float* cur = (wi & 1) ? alphB : alphA;
    const int ws  = (wi & 3) * WIN;
    const int wsn = ((wi + 1) & 3) * WIN;

    // publish owned alpha_(wt-1) (or t=0 init for window 0)
    if (ow0) cur[s0] = a0;
    if (ow1) cur[s1] = a1;

    issue_win(wt + 2 * WIN);   // prefetch 2 windows ahead (slot of window wi-2: readers done)
    cp_wait<1>();              // window wi+1 resident
    __syncthreads();           // publish alpha + cp.async data visibility

    // refresh full strip (fresh halo from neighbor's owned partition)
    a0 = cur[s0];
    a1 = cur[s1];

    // preload emissions for t = wt
    float eb = rows[ws][0]   * LOG2E;
    float ec = rows[ws][cls] * LOG2E;

    #pragma unroll
    for (int j = 0; j < WIN; ++j) {
      const int t = wt + j;
      const int slr = (j + 1 < WIN) ? (ws + j + 1) : wsn;
      float ebn = rows[slr][0];          // next-step emission prefetch (off chain)
      float ecn = rows[slr][cls];
      if (t >= 1 && t < len) {
        float sh = __shfl_up_sync(0xffffffffu, a1, 1);   // alpha[s0-1] == alpha[s1-2]
        sh = lowcut ? NEG2 : sh;
        // even (blank): lse2(a0, sh); max term's exp2 == 1 exactly
        float m0 = fmaxf(a0, sh);
        float n0 = fminf(a0, sh);
        float a0n = m0 + flog2(1.0f + fexp2(n0 - m0)) + eb;
        // odd: lse3(a1, a0, sh2); select the two non-max terms
        float sh2 = skipok ? sh : NEG2;
        float m1 = fmaxf(a1, fmaxf(a0, sh2));
        bool  t1 = (a1 == m1);
        float u  = t1 ? a0  : a1;
        float v  = t1 ? sh2 : ((a0 == m1) ? sh2 : a0);
        float a1n = m1 + flog2(1.0f + fexp2(u - m1) + fexp2(v - m1)) + ec;
        a0 = a0n; a1 = a1n;
      }
      eb = ebn * LOG2E;
      ec = ecn * LOG2E;
    }
  }

  // final: stage alpha_(len-1), extract loss
  __syncthreads();
  if (ow0) alphA[s0] = a0;
  if (ow1) alphA[s1] = a1;
  __syncthreads();

  if (tid == 0) {
    float ahi = alphA[2 * tl];
    float alo = alphA[2 * tl - 1];
    float m  = fmaxf(ahi, alo);
    float mn = fminf(ahi, alo);
    float ll2 = m + flog2(1.0f + fexp2(mn - m));
    float loss = -ll2 * LN2F;
    if (!(loss < 0.5e9f)) loss = 0.f;    // zero_infinity (also inf/nan)
    g_loss[b] = loss / (float)tl;
    __threadfence();
    int old = atomicAdd(&g_done, 1);
    int isl = (old == BB - 1);
    if (isl) g_done = 0;                 // reset for next graph replay
    lastblk = isl;
  }
  __syncthreads();

  if (lastblk) {                         // fused mean over batches in last block
    __threadfence();
    float v = (tid < BB) ? g_loss[tid] : 0.f;
    #pragma unroll
    for (int o = 16; o > 0; o >>= 1) v += __shfl_down_sync(0xffffffffu, v, o);
    if (lane == 0 && w < 4) red[w] = v;
    __syncthreads();
    if (tid == 0) out[0] = (red[0] + red[1] + red[2] + red[3]) * (1.0f / (float)BB);
  }
}

extern "C" void kernel_launch(void* const* d_in, const int* in_sizes, int n_in,
                              void* d_out, int out_size)
{
  const float* lp = (const float*)d_in[0];
  const int*   yy = (const int*)  d_in[1];
  const int*   il = (const int*)  d_in[2];
  const int*   tl = (const int*)  d_in[3];
  ctc_fwd<<<BB, NTHR>>>(lp, yy, il, tl, (float*)d_out);
}

// round 6
// speedup vs baseline: 5.3330x; 1.0667x over previous
#include <cuda_runtime.h>
#include <cstdint>

#define TT 1024
#define BB 128
#define CC 256
#define SS 128
#define NTHR 192        // 6 warps
#define WIN 12          // steps per sync window == halo overlap 24 / 2 states per step
#define LOG2E 1.4426950408889634f
#define LN2F  0.6931471805599453f
#define NEG2  (-1.0e9f)

__device__ float g_loss[BB];
__device__ int   g_done;          // zero-init; nets to zero every launch

static __device__ __forceinline__ float fexp2(float x){ float y; asm("ex2.approx.ftz.f32 %0, %1;" : "=f"(y) : "f"(x)); return y; }
static __device__ __forceinline__ float flog2(float x){ float y; asm("lg2.approx.f32 %0, %1;" : "=f"(y) : "f"(x)); return y; }
static __device__ __forceinline__ void cp16(unsigned dst, const float* src){
  asm volatile("cp.async.cg.shared.global [%0], [%1], 16;" :: "r"(dst), "l"(src));
}
static __device__ __forceinline__ void cp_commit(){ asm volatile("cp.async.commit_group;"); }
template<int N> static __device__ __forceinline__ void cp_wait(){ asm volatile("cp.async.wait_group %0;" :: "n"(N)); }

__global__ void __launch_bounds__(NTHR, 1) ctc_fwd(
    const float* __restrict__ lp, const int* __restrict__ y,
    const int* __restrict__ ilen, const int* __restrict__ tlen,
    float* __restrict__ out)
{
  __shared__ __align__(16) float rows[2 * WIN][CC]; // 24KB emission row ring, 2 windows
  __shared__ float alphA[280];                      // alpha exchange, double-buffered
  __shared__ float alphB[280];
  __shared__ float red[8];
  __shared__ int   lastblk;

  const int b    = blockIdx.x;
  const int tid  = threadIdx.x;
  const int w    = tid >> 5;
  const int lane = tid & 31;
  const int len  = ilen[b];
  const int tl   = tlen[b];

  const int bw = 40 * w;                 // strip base (even state)
  const int s0 = bw + 2 * lane;          // even state (blank)
  const int s1 = s0 + 1;                 // odd state (label)
  const int own_lo = w ? bw + 24 : 0;    // owned partition: [own_lo, bw+64)
  const int own_hi = bw + 64;
  const bool ow0 = (s0 >= own_lo) & (s0 < own_hi);
  const bool ow1 = (s1 >= own_lo) & (s1 < own_hi);
  const bool lowcut = (w == 0) & (lane == 0);   // state 0 has no s-1 (even path only)

  // label class + skip flag for the odd state
  int idx  = s0 >> 1;                    // label index of s1
  int idxc = idx < SS ? idx : SS - 1;
  int im1  = idxc >= 1 ? idxc - 1 : 0;
  int cls  = y[b * SS + idxc];
  int clsp = y[b * SS + im1];
  bool skipok = (idx >= 1) && (idx < SS) && (cls != clsp);

  const float* gb = lp + (size_t)b * CC;
  const unsigned rows_u = (unsigned)__cvta_generic_to_shared(&rows[0][0]);

  // issue one 12-row window as one commit group (768 coalesced 16B chunks)
  auto issue_win = [&](int wt) {
    int bslot = ((wt / WIN) & 1) * WIN;
    #pragma unroll
    for (int k = 0; k < 4; ++k) {
      int c = tid + k * NTHR;            // 0..767
      int r   = c >> 6;
      int off = (c & 63) * 16;
      int row = wt + r;
      if (row < TT)
        cp16(rows_u + (unsigned)((bslot + r) * (CC * 4) + off),
             gb + (size_t)row * (BB * CC) + (off >> 2));
    }
    cp_commit();
  };

  // prologue: window 0 resident
  issue_win(0);
  cp_wait<0>();
  __syncthreads();

  // t=0 init (log2 domain): only global states 0 and 1 reachable
  float a0 = NEG2, a1 = NEG2;
  if (s0 == 0) a0 = rows[0][0]   * LOG2E;
  if (s1 == 1) a1 = rows[0][cls] * LOG2E;

  int wi = 0;
  for (int wt = 0; wt < len; wt += WIN, ++wi) {
    float* cur = (wi & 1) ? alphB : alphA;
    const int ws = (wi & 1) * WIN;

    // publish owned alpha_(wt-1) (or t=0 init for window 0)
    if (ow0) cur[s0] = a0;
    if (ow1) cur[s1] = a1;

    cp_wait<0>();              // window wi resident (issued after previous barrier)
    __syncthreads();           // alpha publish + rows visibility

    issue_win(wt + WIN);       // other slot: its old readers all passed the barrier above

    // refresh full strip (fresh halo from neighbor's owned partition)
    a0 = cur[s0];
    a1 = cur[s1];

    #pragma unroll
    for (int j = 0; j < WIN; ++j) {
      const int t = wt + j;
      // emission loads inline: no smem stores in window -> ptxas hoists/spreads them
      float eb = rows[ws + j][0]   * LOG2E;
      float ec = rows[ws + j][cls] * LOG2E;
      if (t >= 1 && t < len) {
        float sh = __shfl_up_sync(0xffffffffu, a1, 1);  // alpha[s0-1] == alpha[s1-2]
        // even (blank): lse2 with max-trick (1 EX2 + 1 LG2)
        float she = lowcut ? NEG2 : sh;
        float m0 = fmaxf(a0, she);
        float n0 = fminf(a0, she);
        float a0n = m0 + flog2(1.0f + fexp2(n0 - m0)) + eb;
        // odd: plain 3-exp lse3 (shorter dependency cycle, no selects)
        float sh2 = skipok ? sh : NEG2;
        float m1  = fmaxf(a1, fmaxf(a0, sh2));
        float sum = fexp2(a1 - m1) + fexp2(a0 - m1) + fexp2(sh2 - m1);
        float a1n = m1 + flog2(sum) + ec;
        a0 = a0n;
        a1 = a1n;
      }
    }
  }

  // final: stage alpha_(len-1), extract loss
  __syncthreads();
  if (ow0) alphA[s0] = a0;
  if (ow1) alphA[s1] = a1;
  __syncthreads();

  if (tid == 0) {
    float ahi = alphA[2 * tl];
    float alo = alphA[2 * tl - 1];
    float m  = fmaxf(ahi, alo);
    float mn = fminf(ahi, alo);
    float ll2 = m + flog2(1.0f + fexp2(mn - m));
    float loss = -ll2 * LN2F;
    if (!(loss < 0.5e9f)) loss = 0.f;    // zero_infinity (also inf/nan)
    g_loss[b] = loss / (float)tl;
    __threadfence();
    int old = atomicAdd(&g_done, 1);
    int isl = (old == BB - 1);
    if (isl) g_done = 0;                 // reset for next graph replay
    lastblk = isl;
  }
  __syncthreads();

  if (lastblk) {                         // fused mean over batches in last block
    __threadfence();
    float v = (tid < BB) ? g_loss[tid] : 0.f;
    #pragma unroll
    for (int o = 16; o > 0; o >>= 1) v += __shfl_down_sync(0xffffffffu, v, o);
    if (lane == 0 && w < 4) red[w] = v;
    __syncthreads();
    if (tid == 0) out[0] = (red[0] + red[1] + red[2] + red[3]) * (1.0f / (float)BB);
  }
}

extern "C" void kernel_launch(void* const* d_in, const int* in_sizes, int n_in,
                              void* d_out, int out_size)
{
  const float* lp = (const float*)d_in[0];
  const int*   yy = (const int*)  d_in[1];
  const int*   il = (const int*)  d_in[2];
  const int*   tl = (const int*)  d_in[3];
  ctc_fwd<<<BB, NTHR>>>(lp, yy, il, tl, (float*)d_out);
}